// round 2
// baseline (speedup 1.0000x reference)
#include <cuda_runtime.h>
#include <cuda_bf16.h>

// GraphSAGE: 2x SAGEConv(mean) + per-graph mean pooling.
// N=100000 nodes, E=2500000 edges, IN=32, HID=16, OUT=64, 64 graphs.
//
// Pipeline (graph-capturable, scratch in __device__ globals):
//  K0  k_detect : detect whether edge_index/batch are int32 or int64 (JAX x64 off
//                 silently downgrades the declared int64 to int32)
//  K1  k_lin1   : y1 = x@w1_l^T, z1 = x@w1_r^T + b1 ; zero agg/cnt
//  K2  k_edge<1>: agg[dst] += y1[src] (red.v4.f32), cnt[dst] += 1
//  K3  k_h      : h = relu(agg/max(cnt,1) + z1) ; zero agg for phase 2
//  K4  k_edge<2>: agg[dst] += h[src]
//  K5  k_pool   : per-graph block; node_out = (agg/cnt)@w2_l^T + b2 + h@w2_r^T,
//                 mean over contiguous node range (batch sorted -> binary search)

#define N_MAX 100000

__device__ __align__(16) float g_y1 [N_MAX * 16];
__device__ __align__(16) float g_z1 [N_MAX * 16];
__device__ __align__(16) float g_agg[N_MAX * 16];
__device__ __align__(16) float g_h  [N_MAX * 16];
__device__ float g_cnt[N_MAX];
__device__ int   g_idx64;   // 1 if indices are int64, 0 if int32

// ---------------------------------------------------------------- K0
// If buffer holds int64 values < 2^31 (node ids), every odd 32-bit word is 0.
// With random int32 ids in [0,1e5), 256 consecutive odd words all-zero is
// impossible in practice.
__global__ void k_detect(const int* __restrict__ ei_raw) {
    __shared__ int nz;
    if (threadIdx.x == 0) nz = 0;
    __syncthreads();
    int v = ei_raw[2 * threadIdx.x + 1];
    if (v != 0) atomicOr(&nz, 1);
    __syncthreads();
    if (threadIdx.x == 0) g_idx64 = (nz == 0) ? 1 : 0;
}

__device__ __forceinline__ int load_idx(const void* p, long long i, int is64) {
    if (is64) return (int)((const long long*)p)[i];
    return ((const int*)p)[i];
}

// ---------------------------------------------------------------- K1
__global__ void k_lin1(const float* __restrict__ x,
                       const float* __restrict__ w1l,
                       const float* __restrict__ b1,
                       const float* __restrict__ w1r,
                       int n) {
    __shared__ float swl[16 * 32];
    __shared__ float swr[16 * 32];
    __shared__ float sb[16];
    for (int i = threadIdx.x; i < 512; i += blockDim.x) {
        swl[i] = w1l[i];
        swr[i] = w1r[i];
    }
    if (threadIdx.x < 16) sb[threadIdx.x] = b1[threadIdx.x];
    __syncthreads();

    int node = blockIdx.x * blockDim.x + threadIdx.x;
    if (node >= n) return;

    float xr[32];
    const float4* xp = reinterpret_cast<const float4*>(x) + node * 8;
#pragma unroll
    for (int j = 0; j < 8; j++) {
        float4 v = xp[j];
        xr[4 * j + 0] = v.x; xr[4 * j + 1] = v.y;
        xr[4 * j + 2] = v.z; xr[4 * j + 3] = v.w;
    }

    float y[16], z[16];
#pragma unroll
    for (int o = 0; o < 16; o++) {
        float a = 0.f, b = 0.f;
#pragma unroll
        for (int k = 0; k < 32; k++) {
            a = fmaf(xr[k], swl[o * 32 + k], a);
            b = fmaf(xr[k], swr[o * 32 + k], b);
        }
        y[o] = a;
        z[o] = b + sb[o];
    }

    float4* yp = reinterpret_cast<float4*>(g_y1)  + node * 4;
    float4* zp = reinterpret_cast<float4*>(g_z1)  + node * 4;
    float4* ap = reinterpret_cast<float4*>(g_agg) + node * 4;
#pragma unroll
    for (int j = 0; j < 4; j++) {
        yp[j] = make_float4(y[4*j], y[4*j+1], y[4*j+2], y[4*j+3]);
        zp[j] = make_float4(z[4*j], z[4*j+1], z[4*j+2], z[4*j+3]);
        ap[j] = make_float4(0.f, 0.f, 0.f, 0.f);
    }
    g_cnt[node] = 0.f;
}

// ---------------------------------------------------------------- K2/K4
// 4 lanes per edge; each lane handles 4 channels via red.global.add.v4.f32.
template <int PHASE>
__global__ void k_edge(const void* __restrict__ ei, int E) {
    int t = blockIdx.x * blockDim.x + threadIdx.x;
    int e = t >> 2;
    int q = t & 3;
    if (e >= E) return;

    int is64 = g_idx64;   // uniform branch
    int s = load_idx(ei, e, is64);
    int d = load_idx(ei, (long long)E + e, is64);

    const float* feat = (PHASE == 1) ? g_y1 : g_h;
    float4 v = reinterpret_cast<const float4*>(feat)[s * 4 + q];

    float* p = g_agg + d * 16 + q * 4;
    asm volatile("red.global.add.v4.f32 [%0], {%1,%2,%3,%4};"
                 :: "l"(p), "f"(v.x), "f"(v.y), "f"(v.z), "f"(v.w)
                 : "memory");

    if (PHASE == 1 && q == 0) atomicAdd(&g_cnt[d], 1.0f);
}

// ---------------------------------------------------------------- K3
__global__ void k_h(int n) {
    int t = blockIdx.x * blockDim.x + threadIdx.x;
    if (t >= n * 16) return;
    int node = t >> 4;
    float c = fmaxf(g_cnt[node], 1.0f);
    float v = g_agg[t] / c + g_z1[t];
    g_h[t] = fmaxf(v, 0.0f);
    g_agg[t] = 0.0f;   // reset for phase 2 (this thread owns this element)
}

// ---------------------------------------------------------------- K5
// One block per graph. 256 threads = 64 channels x 4 node-lanes.
__global__ void k_pool(const void* __restrict__ batch,
                       const float* __restrict__ w2l,
                       const float* __restrict__ b2,
                       const float* __restrict__ w2r,
                       float* __restrict__ out, int n) {
    __shared__ __align__(16) float snode[4][32]; // [lane][0..15]=agg_mean, [16..31]=h
    __shared__ float sred[256];
    __shared__ int   sse[2];

    int tid = threadIdx.x;
    int g   = blockIdx.x;

    if (tid < 2) {
        int is64 = g_idx64;
        int v = g + tid;
        int lo = 0, hi = n;
        while (lo < hi) {
            int mid = (lo + hi) >> 1;
            if (load_idx(batch, mid, is64) < v) lo = mid + 1; else hi = mid;
        }
        sse[tid] = lo;
    }

    int c    = tid & 63;
    int lane = tid >> 6;

    float wl[16], wr[16];
#pragma unroll
    for (int k = 0; k < 16; k++) {
        wl[k] = w2l[c * 16 + k];
        wr[k] = w2r[c * 16 + k];
    }
    __syncthreads();

    int s = sse[0], e = sse[1];
    float acc = 0.f;

    for (int base = s; base < e; base += 4) {
        __syncthreads();             // protect snode vs previous iteration's readers
        if (tid < 128) {
            int nl = tid >> 5, f = tid & 31;
            int node = base + nl;
            float v = 0.f;
            if (node < e) {
                if (f < 16) v = g_agg[node * 16 + f] / fmaxf(g_cnt[node], 1.0f);
                else        v = g_h[node * 16 + (f - 16)];
            }
            snode[nl][f] = v;
        }
        __syncthreads();
        if (base + lane < e) {
            const float4* pa = reinterpret_cast<const float4*>(&snode[lane][0]);
            const float4* ph = reinterpret_cast<const float4*>(&snode[lane][16]);
#pragma unroll
            for (int j = 0; j < 4; j++) {
                float4 a = pa[j];
                float4 h = ph[j];
                acc = fmaf(a.x, wl[4*j+0], acc);
                acc = fmaf(a.y, wl[4*j+1], acc);
                acc = fmaf(a.z, wl[4*j+2], acc);
                acc = fmaf(a.w, wl[4*j+3], acc);
                acc = fmaf(h.x, wr[4*j+0], acc);
                acc = fmaf(h.y, wr[4*j+1], acc);
                acc = fmaf(h.z, wr[4*j+2], acc);
                acc = fmaf(h.w, wr[4*j+3], acc);
            }
        }
    }

    sred[tid] = acc;
    __syncthreads();
    if (lane == 0) {
        float tot = sred[c] + sred[64 + c] + sred[128 + c] + sred[192 + c];
        float cg  = (float)(e - s);
        out[g * 64 + c] = (tot + b2[c] * cg) / fmaxf(cg, 1.0f);
    }
}

// ---------------------------------------------------------------- launch
extern "C" void kernel_launch(void* const* d_in, const int* in_sizes, int n_in,
                              void* d_out, int out_size) {
    const float* x     = (const float*)d_in[0];
    const void*  ei    = d_in[1];
    const void*  batch = d_in[2];
    const float* w1l   = (const float*)d_in[3];
    const float* b1    = (const float*)d_in[4];
    const float* w1r   = (const float*)d_in[5];
    const float* w2l   = (const float*)d_in[6];
    const float* b2    = (const float*)d_in[7];
    const float* w2r   = (const float*)d_in[8];
    float*       out   = (float*)d_out;

    int n = in_sizes[0] / 32;        // 100000
    int E = in_sizes[1] / 2;         // 2500000

    k_detect<<<1, 256>>>((const int*)ei);

    k_lin1<<<(n + 127) / 128, 128>>>(x, w1l, b1, w1r, n);

    int edge_threads = E * 4;
    k_edge<1><<<(edge_threads + 255) / 256, 256>>>(ei, E);

    k_h<<<(n * 16 + 255) / 256, 256>>>(n);

    k_edge<2><<<(edge_threads + 255) / 256, 256>>>(ei, E);

    k_pool<<<64, 256>>>(batch, w2l, b2, w2r, out, n);
}

// round 3
// speedup vs baseline: 2.8090x; 2.8090x over previous
#include <cuda_runtime.h>
#include <cuda_bf16.h>

// GraphSAGE: 2x SAGEConv(mean) + per-graph mean pool. CSR-gather formulation.
//
//  K0 k_init   : detect idx dtype (int32 vs int64); zero deg/S1/S2
//  K1 k_lin1   : y1 = x@w1_l^T ; z1 = x@w1_r^T + b1
//  K2 k_hist   : deg[dst]++                       (int RED)
//  K3-K5 scan  : rowptr = exclusive_scan(deg); cursor = rowptr
//  K6 k_scatter: col[cursor[dst]++] = src         (CSR build)
//  K7 k_gather1: h = relu( mean_{src in N(d)} y1[src] + z1[d] )
//  K8 k_gather2: a2[d] = mean_{src} h[src]; per-graph S1 += a2, S2 += h[d]
//  K9 k_final  : out[g] = (S1/cnt)@w2l^T + b2 + (S2/cnt)@w2r^T

#define N_MAX 100000
#define E_MAX 2500000
#define SCAN_B 256

__device__ __align__(16) float g_y1 [N_MAX * 16];
__device__ __align__(16) float g_z1 [N_MAX * 16];
__device__ __align__(16) float g_h  [N_MAX * 16];
__device__ int   g_deg   [N_MAX];
__device__ int   g_scan  [N_MAX];
__device__ int   g_rowptr[N_MAX];
__device__ int   g_cursor[N_MAX];
__device__ int   g_col   [E_MAX];
__device__ int   g_bsum  [(N_MAX + SCAN_B - 1) / SCAN_B];
__device__ int   g_boff  [(N_MAX + SCAN_B - 1) / SCAN_B];
__device__ float g_S1[64 * 16];
__device__ float g_S2[64 * 16];
__device__ int   g_idx64;

__device__ __forceinline__ int load_idx(const void* p, long long i, int is64) {
    if (is64) return (int)((const long long*)p)[i];
    return ((const int*)p)[i];
}

// ---------------------------------------------------------------- K0
__global__ void k_init(const int* __restrict__ ei_raw, int n) {
    if (blockIdx.x == 0 && threadIdx.x < 256) {
        // int64 node ids < 2^31 -> every odd 32-bit word is 0
        __shared__ int nz;
        if (threadIdx.x == 0) nz = 0;
        __syncthreads();
        if (ei_raw[2 * threadIdx.x + 1] != 0) atomicOr(&nz, 1);
        __syncthreads();
        if (threadIdx.x == 0) g_idx64 = (nz == 0) ? 1 : 0;
    }
    int i = blockIdx.x * blockDim.x + threadIdx.x;
    if (i < n) g_deg[i] = 0;
    if (i < 64 * 16) { g_S1[i] = 0.f; g_S2[i] = 0.f; }
}

// ---------------------------------------------------------------- K1
__global__ void k_lin1(const float* __restrict__ x,
                       const float* __restrict__ w1l,
                       const float* __restrict__ b1,
                       const float* __restrict__ w1r,
                       int n) {
    __shared__ float swl[512], swr[512], sb[16];
    for (int i = threadIdx.x; i < 512; i += blockDim.x) {
        swl[i] = w1l[i];
        swr[i] = w1r[i];
    }
    if (threadIdx.x < 16) sb[threadIdx.x] = b1[threadIdx.x];
    __syncthreads();

    int node = blockIdx.x * blockDim.x + threadIdx.x;
    if (node >= n) return;

    float xr[32];
    const float4* xp = reinterpret_cast<const float4*>(x) + node * 8;
#pragma unroll
    for (int j = 0; j < 8; j++) {
        float4 v = xp[j];
        xr[4*j+0] = v.x; xr[4*j+1] = v.y; xr[4*j+2] = v.z; xr[4*j+3] = v.w;
    }

    float y[16], z[16];
#pragma unroll
    for (int o = 0; o < 16; o++) {
        float a = 0.f, b = 0.f;
#pragma unroll
        for (int k = 0; k < 32; k++) {
            a = fmaf(xr[k], swl[o * 32 + k], a);
            b = fmaf(xr[k], swr[o * 32 + k], b);
        }
        y[o] = a;
        z[o] = b + sb[o];
    }

    float4* yp = reinterpret_cast<float4*>(g_y1) + node * 4;
    float4* zp = reinterpret_cast<float4*>(g_z1) + node * 4;
#pragma unroll
    for (int j = 0; j < 4; j++) {
        yp[j] = make_float4(y[4*j], y[4*j+1], y[4*j+2], y[4*j+3]);
        zp[j] = make_float4(z[4*j], z[4*j+1], z[4*j+2], z[4*j+3]);
    }
}

// ---------------------------------------------------------------- K2
__global__ void k_hist(const void* __restrict__ ei, int E) {
    int t = blockIdx.x * blockDim.x + threadIdx.x;
    if (t >= E) return;
    int d = load_idx(ei, (long long)E + t, g_idx64);
    atomicAdd(&g_deg[d], 1);           // no result used -> RED
}

// ---------------------------------------------------------------- K3..K5 scan
__global__ void k_scanA(int n) {
    __shared__ int sm[SCAN_B];
    int tid = threadIdx.x;
    int i = blockIdx.x * SCAN_B + tid;
    int v = (i < n) ? g_deg[i] : 0;
    sm[tid] = v;
    __syncthreads();
#pragma unroll
    for (int off = 1; off < SCAN_B; off <<= 1) {
        int t = (tid >= off) ? sm[tid - off] : 0;
        __syncthreads();
        sm[tid] += t;
        __syncthreads();
    }
    if (i < n) g_scan[i] = sm[tid];
    if (tid == SCAN_B - 1) g_bsum[blockIdx.x] = sm[tid];
}

__global__ void k_scanB(int nb) {       // 1 block, 512 threads (nb <= 512)
    __shared__ int sm[512];
    int tid = threadIdx.x;
    int v = (tid < nb) ? g_bsum[tid] : 0;
    sm[tid] = v;
    __syncthreads();
#pragma unroll
    for (int off = 1; off < 512; off <<= 1) {
        int t = (tid >= off) ? sm[tid - off] : 0;
        __syncthreads();
        sm[tid] += t;
        __syncthreads();
    }
    if (tid < nb) g_boff[tid] = sm[tid] - v;   // exclusive
}

__global__ void k_scanC(int n) {
    int i = blockIdx.x * SCAN_B + threadIdx.x;
    if (i >= n) return;
    int ex = g_scan[i] - g_deg[i] + g_boff[blockIdx.x];
    g_rowptr[i] = ex;
    g_cursor[i] = ex;
}

// ---------------------------------------------------------------- K6
__global__ void k_scatter(const void* __restrict__ ei, int E) {
    int t = blockIdx.x * blockDim.x + threadIdx.x;
    if (t >= E) return;
    int is64 = g_idx64;
    int s = load_idx(ei, t, is64);
    int d = load_idx(ei, (long long)E + t, is64);
    int slot = atomicAdd(&g_cursor[d], 1);
    g_col[slot] = s;
}

// ---------------------------------------------------------------- K7
__global__ void k_gather1(int n) {
    int t = blockIdx.x * blockDim.x + threadIdx.x;
    int node = t >> 2, q = t & 3;
    if (node >= n) return;

    int base = g_rowptr[node];
    int deg  = g_deg[node];
    const float4* feat = reinterpret_cast<const float4*>(g_y1);

    float4 acc = make_float4(0.f, 0.f, 0.f, 0.f);
#pragma unroll 4
    for (int i = 0; i < deg; i++) {
        int s = __ldg(&g_col[base + i]);
        float4 v = feat[s * 4 + q];
        acc.x += v.x; acc.y += v.y; acc.z += v.z; acc.w += v.w;
    }
    float inv = 1.0f / (float)max(deg, 1);
    float4 z = reinterpret_cast<const float4*>(g_z1)[node * 4 + q];
    float4 h;
    h.x = fmaxf(fmaf(acc.x, inv, z.x), 0.f);
    h.y = fmaxf(fmaf(acc.y, inv, z.y), 0.f);
    h.z = fmaxf(fmaf(acc.z, inv, z.z), 0.f);
    h.w = fmaxf(fmaf(acc.w, inv, z.w), 0.f);
    reinterpret_cast<float4*>(g_h)[node * 4 + q] = h;
}

// ---------------------------------------------------------------- K8
// 256 threads = 64 contiguous nodes x 4 quads. Per-graph partial sums in smem
// (batch sorted -> local graph index bounded by 64), then global RED flush.
__global__ void k_gather2(const void* __restrict__ batch, int n) {
    __shared__ float Sa[65 * 16];
    __shared__ float Sh[65 * 16];
    __shared__ int s_g0, s_span;

    int tid = threadIdx.x;
    int node0 = blockIdx.x * 64;
    int node = node0 + (tid >> 2), q = tid & 3;
    int is64 = g_idx64;

    for (int i = tid; i < 65 * 16; i += 256) { Sa[i] = 0.f; Sh[i] = 0.f; }
    if (tid == 0) {
        int g0 = load_idx(batch, node0, is64);
        int nl = min(node0 + 63, n - 1);
        s_g0 = g0;
        s_span = load_idx(batch, nl, is64) - g0;
    }
    __syncthreads();

    if (node < n) {
        int base = g_rowptr[node];
        int deg  = g_deg[node];
        const float4* feat = reinterpret_cast<const float4*>(g_h);

        float4 acc = make_float4(0.f, 0.f, 0.f, 0.f);
#pragma unroll 4
        for (int i = 0; i < deg; i++) {
            int s = __ldg(&g_col[base + i]);
            float4 v = feat[s * 4 + q];
            acc.x += v.x; acc.y += v.y; acc.z += v.z; acc.w += v.w;
        }
        float inv = 1.0f / (float)max(deg, 1);
        float4 hv = feat[node * 4 + q];

        int gl = load_idx(batch, node, is64) - s_g0;
        float* pa = &Sa[gl * 16 + q * 4];
        float* ph = &Sh[gl * 16 + q * 4];
        atomicAdd(pa + 0, acc.x * inv); atomicAdd(pa + 1, acc.y * inv);
        atomicAdd(pa + 2, acc.z * inv); atomicAdd(pa + 3, acc.w * inv);
        atomicAdd(ph + 0, hv.x);        atomicAdd(ph + 1, hv.y);
        atomicAdd(ph + 2, hv.z);        atomicAdd(ph + 3, hv.w);
    }
    __syncthreads();

    int tot = (s_span + 1) * 16;
    for (int j = tid; j < tot; j += 256) {
        int gidx = (s_g0 << 4) + j;    // (s_g0 + gl)*16 + c
        atomicAdd(&g_S1[gidx], Sa[j]); // RED
        atomicAdd(&g_S2[gidx], Sh[j]);
    }
}

// ---------------------------------------------------------------- K9
__global__ void k_final(const void* __restrict__ batch,
                        const float* __restrict__ w2l,
                        const float* __restrict__ b2,
                        const float* __restrict__ w2r,
                        float* __restrict__ out, int n) {
    __shared__ float s1[16], s2[16];
    __shared__ int se[2];
    int g = blockIdx.x, c = threadIdx.x;
    int is64 = g_idx64;

    if (c < 2) {
        int v = g + c;
        int lo = 0, hi = n;
        while (lo < hi) {
            int mid = (lo + hi) >> 1;
            if (load_idx(batch, mid, is64) < v) lo = mid + 1; else hi = mid;
        }
        se[c] = lo;
    }
    if (c < 16) { s1[c] = g_S1[g * 16 + c]; s2[c] = g_S2[g * 16 + c]; }
    __syncthreads();

    int cnt = se[1] - se[0];
    float ic = 1.0f / (float)max(cnt, 1);
    float acc = (cnt > 0) ? b2[c] : 0.f;
#pragma unroll
    for (int k = 0; k < 16; k++) {
        acc = fmaf(s1[k] * ic, w2l[c * 16 + k], acc);
        acc = fmaf(s2[k] * ic, w2r[c * 16 + k], acc);
    }
    out[g * 64 + c] = acc;
}

// ---------------------------------------------------------------- launch
extern "C" void kernel_launch(void* const* d_in, const int* in_sizes, int n_in,
                              void* d_out, int out_size) {
    const float* x     = (const float*)d_in[0];
    const void*  ei    = d_in[1];
    const void*  batch = d_in[2];
    const float* w1l   = (const float*)d_in[3];
    const float* b1    = (const float*)d_in[4];
    const float* w1r   = (const float*)d_in[5];
    const float* w2l   = (const float*)d_in[6];
    const float* b2    = (const float*)d_in[7];
    const float* w2r   = (const float*)d_in[8];
    float*       out   = (float*)d_out;

    int n = in_sizes[0] / 32;   // 100000
    int E = in_sizes[1] / 2;    // 2500000
    int nb = (n + SCAN_B - 1) / SCAN_B;

    k_init   <<<(n + 1023) / 1024, 1024>>>((const int*)ei, n);
    k_lin1   <<<(n + 127) / 128, 128>>>(x, w1l, b1, w1r, n);
    k_hist   <<<(E + 255) / 256, 256>>>(ei, E);
    k_scanA  <<<nb, SCAN_B>>>(n);
    k_scanB  <<<1, 512>>>(nb);
    k_scanC  <<<nb, SCAN_B>>>(n);
    k_scatter<<<(E + 255) / 256, 256>>>(ei, E);
    k_gather1<<<(n * 4 + 255) / 256, 256>>>(n);
    k_gather2<<<(n + 63) / 64, 256>>>(batch, n);
    k_final  <<<64, 64>>>(batch, w2l, b2, w2r, out, n);
}